// round 3
// baseline (speedup 1.0000x reference)
#include <cuda_runtime.h>
#include <cuda_bf16.h>

// SoftEmbeddedDecisionRules: balanced binary hierarchy over C=1024 classes.
// One row per warp; per-lane-contiguous compute layout (MUFU-minimal);
// smem-swizzled staging for coalesced global I/O; sigmoids computed eagerly
// in the upsweep so raw logits/sums die early (register pressure ~40 live).

#define BATCH_N 32768
#define NCLASS 1024
#define WARPS_PER_BLOCK 8

__device__ __forceinline__ float sigmoidf_fast(float x) {
    return __fdividef(1.0f, 1.0f + __expf(-x));
}

// 16B-chunk swizzle: conflict-free for both (c = 32j+lane) and (c = 8*lane+i)
__device__ __forceinline__ int swz(int c) { return c ^ ((c >> 3) & 7); }

__global__ void __launch_bounds__(WARPS_PER_BLOCK * 32, 5)
soft_tree_kernel(const float* __restrict__ in, float* __restrict__ out) {
    __shared__ float4 buf[WARPS_PER_BLOCK][256];

    const int wib  = threadIdx.x >> 5;
    const int lane = threadIdx.x & 31;
    const int row  = blockIdx.x * WARPS_PER_BLOCK + wib;

    const float4* gin = reinterpret_cast<const float4*>(in + (size_t)row * NCLASS);

    // ---- coalesced load -> swizzled smem (t dies immediately after STS) ----
#pragma unroll
    for (int j = 0; j < 8; j++) {
        float4 t = gin[j * 32 + lane];
        buf[wib][swz(j * 32 + lane)] = t;
    }
    __syncwarp();

    // ---- phase A: read per-lane-contiguous, compute s2 + leaf sigmoids ----
    float s2[16], a1[16];
#pragma unroll
    for (int i = 0; i < 8; i++) {
        float4 q = buf[wib][swz(lane * 8 + i)];
        s2[2 * i + 0] = q.x + q.y;
        a1[2 * i + 0] = sigmoidf_fast(q.x - q.y);
        s2[2 * i + 1] = q.z + q.w;
        a1[2 * i + 1] = sigmoidf_fast(q.z - q.w);
    }

    // ---- upsweep with eager sigmoids: each sN dies after its level ----
    float s4[8], a2[8];
#pragma unroll
    for (int i = 0; i < 8; i++) {
        s4[i] = s2[2 * i] + s2[2 * i + 1];
        a2[i] = sigmoidf_fast((s2[2 * i] - s2[2 * i + 1]) * 0.5f);
    }
    float s8[4], a4[4];
#pragma unroll
    for (int i = 0; i < 4; i++) {
        s8[i] = s4[2 * i] + s4[2 * i + 1];
        a4[i] = sigmoidf_fast((s4[2 * i] - s4[2 * i + 1]) * 0.25f);
    }
    float s16[2], a8[2];
#pragma unroll
    for (int i = 0; i < 2; i++) {
        s16[i] = s8[2 * i] + s8[2 * i + 1];
        a8[i] = sigmoidf_fast((s8[2 * i] - s8[2 * i + 1]) * 0.125f);
    }
    float S   = s16[0] + s16[1];
    float a16 = sigmoidf_fast((s16[0] - s16[1]) * 0.0625f);

    // ---- cross-lane levels: seg = 32, 64, 128, 256, 512 ----
    float F = 1.0f;
    {
        float o;
        o = __shfl_xor_sync(0xffffffffu, S, 1);
        F *= sigmoidf_fast((S - o) * (1.0f / 32.0f));  S += o;
        o = __shfl_xor_sync(0xffffffffu, S, 2);
        F *= sigmoidf_fast((S - o) * (1.0f / 64.0f));  S += o;
        o = __shfl_xor_sync(0xffffffffu, S, 4);
        F *= sigmoidf_fast((S - o) * (1.0f / 128.0f)); S += o;
        o = __shfl_xor_sync(0xffffffffu, S, 8);
        F *= sigmoidf_fast((S - o) * (1.0f / 256.0f)); S += o;
        o = __shfl_xor_sync(0xffffffffu, S, 16);
        F *= sigmoidf_fast((S - o) * (1.0f / 512.0f));
    }

    // ---- downsweep: multiply sigmoid factors top-down ----
    float p16[2];
    p16[0] = F * a16;
    p16[1] = F - p16[0];

    float p8[4];
#pragma unroll
    for (int i = 0; i < 2; i++) {
        p8[2 * i]     = p16[i] * a8[i];
        p8[2 * i + 1] = p16[i] - p8[2 * i];
    }
    float p4[8];
#pragma unroll
    for (int i = 0; i < 4; i++) {
        p4[2 * i]     = p8[i] * a4[i];
        p4[2 * i + 1] = p8[i] - p4[2 * i];
    }
    float p2[16];
#pragma unroll
    for (int i = 0; i < 8; i++) {
        p2[2 * i]     = p4[i] * a2[i];
        p2[2 * i + 1] = p4[i] - p2[2 * i];
    }

    // leaves -> smem (swizzled), then coalesced store
    __syncwarp();
#pragma unroll
    for (int i = 0; i < 8; i++) {
        float4 w;
        w.x = p2[2 * i] * a1[2 * i];
        w.y = p2[2 * i] - w.x;
        w.z = p2[2 * i + 1] * a1[2 * i + 1];
        w.w = p2[2 * i + 1] - w.z;
        buf[wib][swz(lane * 8 + i)] = w;
    }
    __syncwarp();

    float4* gout = reinterpret_cast<float4*>(out + (size_t)row * NCLASS);
#pragma unroll
    for (int j = 0; j < 8; j++) {
        gout[j * 32 + lane] = buf[wib][swz(j * 32 + lane)];
    }
}

extern "C" void kernel_launch(void* const* d_in, const int* in_sizes, int n_in,
                              void* d_out, int out_size) {
    (void)in_sizes; (void)n_in; (void)out_size;
    const float* in = (const float*)d_in[0];
    float* out = (float*)d_out;
    soft_tree_kernel<<<BATCH_N / WARPS_PER_BLOCK, WARPS_PER_BLOCK * 32>>>(in, out);
}